// round 1
// baseline (speedup 1.0000x reference)
#include <cuda_runtime.h>
#include <math.h>

#define NBATCH 4
#define HH 128
#define WWW 128
#define CC 512
#define NN 16384            // H*W
#define NHEADS 8
#define DHEAD 64
#define MTOT (NBATCH*NN)    // 65536

// ---------------- scratch (device globals; no allocation allowed) -----------
__device__ float g_xm[MTOT*CC];      // modulated x; later reused for v = v_inp*illu
__device__ float g_q [MTOT*CC];
__device__ float g_k [MTOT*CC];
__device__ float g_vi[MTOT*CC];      // v_inp (pre-illu), needed by PE branch
__device__ float g_pe1[MTOT*CC];
__device__ float g_tmp[NBATCH*2048];
__device__ float g_cdp[NBATCH*1024];
__device__ float g_gram[NBATCH*NHEADS*64*64];
__device__ float g_ssq[NBATCH*NHEADS*64];
__device__ float g_ssk[NBATCH*NHEADS*64];
__device__ float g_attn[NBATCH*NHEADS*64*64];
__device__ float g_wfold[NBATCH*CC*CC];

// ---------------- zero accumulators (deterministic each launch) -------------
__global__ void zero_small_k() {
    int i = blockIdx.x*blockDim.x + threadIdx.x;
    if (i < NBATCH*NHEADS*64*64) g_gram[i] = 0.f;
    if (i < NBATCH*NHEADS*64) { g_ssq[i] = 0.f; g_ssk[i] = 0.f; }
}

// ---------------- tiny dense: out[b, j] = sum_k A[b,k] * W[k,j] -------------
__global__ void small_gemm_k(const float* __restrict__ A, const float* __restrict__ Wm,
                             float* __restrict__ out, int K, int Nc) {
    int idx = blockIdx.x*blockDim.x + threadIdx.x;
    if (idx >= NBATCH*Nc) return;
    int b = idx / Nc, j = idx - b*Nc;
    const float* a = A + b*K;
    float acc = 0.f;
    for (int k = 0; k < K; ++k) acc = fmaf(a[k], Wm[k*Nc + j], acc);
    out[idx] = acc;
}

// ---------------- xm = x * cdp1 + cdp2  (per-batch channel affine) ----------
__global__ void modulate_k(const float* __restrict__ x) {
    long long i = (long long)blockIdx.x*blockDim.x + threadIdx.x;   // float4 index
    long long e = i*4;
    int c = (int)(e & (CC-1));
    int b = (int)(e >> 23);          // e / (16384*512)
    float4 xv = ((const float4*)x)[i];
    float4 s = *(const float4*)&g_cdp[b*1024 + c];
    float4 t = *(const float4*)&g_cdp[b*1024 + 512 + c];
    float4 r;
    r.x = fmaf(xv.x, s.x, t.x); r.y = fmaf(xv.y, s.y, t.y);
    r.z = fmaf(xv.z, s.z, t.z); r.w = fmaf(xv.w, s.w, t.w);
    ((float4*)g_xm)[i] = r;
}

// ---------------- v = v_inp * illu  (into g_xm, which is free now) ----------
__global__ void vmul_k(const float* __restrict__ illu) {
    long long i = (long long)blockIdx.x*blockDim.x + threadIdx.x;
    float4 a = ((const float4*)g_vi)[i];
    float4 m = ((const float4*)illu)[i];
    float4 r; r.x = a.x*m.x; r.y = a.y*m.y; r.z = a.z*m.z; r.w = a.w*m.w;
    ((float4*)g_xm)[i] = r;
}

// ---------------- SGEMM: C[M,512] = A[M,512] @ W[512,512] (+bias) -----------
// BM=BN=128, BK=8, 256 threads, 8x8 microtile. PERB: W is per-batch (b = m/16384).
template<bool PERB, bool BIAS>
__global__ __launch_bounds__(256) void sgemm_k(const float* __restrict__ A,
                                               const float* __restrict__ Wm,
                                               const float* __restrict__ bias,
                                               float* __restrict__ Co) {
    __shared__ float As[8][128];
    __shared__ float Bs[8][128];
    int tid = threadIdx.x;
    int n0 = blockIdx.x * 128;
    int m0 = blockIdx.y * 128;
    const float* Wp = Wm;
    if (PERB) Wp += (size_t)(m0 >> 14) * (512*512);

    int irA = tid >> 1, icA = (tid & 1) * 4;     // A tile load: 128 rows x 8 cols
    int irB = tid >> 5, icB = (tid & 31) * 4;    // B tile load: 8 rows x 128 cols
    int tr = tid >> 4, tc = tid & 15;

    float acc[8][8];
    #pragma unroll
    for (int i = 0; i < 8; ++i)
        #pragma unroll
        for (int j = 0; j < 8; ++j) acc[i][j] = 0.f;

    const float* Aptr = A + (size_t)(m0 + irA)*512 + icA;
    const float* Bptr = Wp + (size_t)irB*512 + n0 + icB;

    for (int k0 = 0; k0 < 512; k0 += 8) {
        float4 av = *(const float4*)(Aptr + k0);
        float4 bv = *(const float4*)(Bptr + (size_t)k0*512);
        As[icA+0][irA] = av.x; As[icA+1][irA] = av.y;
        As[icA+2][irA] = av.z; As[icA+3][irA] = av.w;
        *(float4*)&Bs[irB][icB] = bv;
        __syncthreads();
        #pragma unroll
        for (int kk = 0; kk < 8; ++kk) {
            float ra[8], rb[8];
            *(float4*)(ra)   = *(const float4*)&As[kk][tr*8];
            *(float4*)(ra+4) = *(const float4*)&As[kk][tr*8+4];
            *(float4*)(rb)   = *(const float4*)&Bs[kk][tc*8];
            *(float4*)(rb+4) = *(const float4*)&Bs[kk][tc*8+4];
            #pragma unroll
            for (int i = 0; i < 8; ++i)
                #pragma unroll
                for (int j = 0; j < 8; ++j)
                    acc[i][j] = fmaf(ra[i], rb[j], acc[i][j]);
        }
        __syncthreads();
    }

    float bb[8];
    #pragma unroll
    for (int j = 0; j < 8; ++j) bb[j] = BIAS ? bias[n0 + tc*8 + j] : 0.f;

    #pragma unroll
    for (int i = 0; i < 8; ++i) {
        float* cp = Co + (size_t)(m0 + tr*8 + i)*512 + n0 + tc*8;
        float4 v0, v1;
        v0.x = acc[i][0]+bb[0]; v0.y = acc[i][1]+bb[1];
        v0.z = acc[i][2]+bb[2]; v0.w = acc[i][3]+bb[3];
        v1.x = acc[i][4]+bb[4]; v1.y = acc[i][5]+bb[5];
        v1.z = acc[i][6]+bb[6]; v1.w = acc[i][7]+bb[7];
        *(float4*)cp = v0; *(float4*)(cp+4) = v1;
    }
}

// ---------------- Gram: G[bh,i,j] = sum_n k[b,n,h*64+i]*q[b,n,h*64+j] -------
// plus per-column sum of squares for q and k. 32 bh * 8 n-chunks blocks.
__global__ __launch_bounds__(256) void gram_k() {
    int bh = blockIdx.x >> 3;
    int chunk = blockIdx.x & 7;
    int b = bh >> 3, h = bh & 7;
    int tid = threadIdx.x;
    __shared__ float qs[4][64], ks[4][64];
    float acc[4][4] = {{0.f}};
    float sq = 0.f, sk = 0.f;
    int ti = tid >> 4, tj = tid & 15;
    const float* qbase = g_q + (size_t)b*NN*512 + h*64;
    const float* kbase = g_k + (size_t)b*NN*512 + h*64;
    int n0 = chunk * 2048;
    for (int n = n0; n < n0 + 2048; n += 4) {
        __syncthreads();
        #pragma unroll
        for (int l = tid; l < 512; l += 256) {
            int nn = l >> 7, idx = l & 127;
            if (idx < 64) qs[nn][idx]     = qbase[(size_t)(n+nn)*512 + idx];
            else          ks[nn][idx-64]  = kbase[(size_t)(n+nn)*512 + idx - 64];
        }
        __syncthreads();
        #pragma unroll
        for (int nn = 0; nn < 4; ++nn) {
            float kv[4], qv[4];
            #pragma unroll
            for (int ii = 0; ii < 4; ++ii) kv[ii] = ks[nn][ti*4+ii];
            #pragma unroll
            for (int jj = 0; jj < 4; ++jj) qv[jj] = qs[nn][tj*4+jj];
            #pragma unroll
            for (int ii = 0; ii < 4; ++ii)
                #pragma unroll
                for (int jj = 0; jj < 4; ++jj)
                    acc[ii][jj] = fmaf(kv[ii], qv[jj], acc[ii][jj]);
        }
        if (tid < 64) {
            #pragma unroll
            for (int nn = 0; nn < 4; ++nn) sq = fmaf(qs[nn][tid], qs[nn][tid], sq);
        } else if (tid < 128) {
            #pragma unroll
            for (int nn = 0; nn < 4; ++nn) sk = fmaf(ks[nn][tid-64], ks[nn][tid-64], sk);
        }
    }
    float* gp = g_gram + (size_t)bh*4096;
    #pragma unroll
    for (int ii = 0; ii < 4; ++ii)
        #pragma unroll
        for (int jj = 0; jj < 4; ++jj)
            atomicAdd(&gp[(ti*4+ii)*64 + tj*4+jj], acc[ii][jj]);
    if (tid < 64) atomicAdd(&g_ssq[bh*64 + tid], sq);
    else if (tid < 128) atomicAdd(&g_ssk[bh*64 + tid - 64], sk);
}

// ---------------- softmax over j of G[i,j]/(||k_i||*||q_j||)*rescale --------
__global__ void softmax_k(const float* __restrict__ rescale) {
    int bh = blockIdx.x;
    int h = bh & 7;
    int i = threadIdx.x;            // 64 threads
    __shared__ float rq[64];
    rq[i] = 1.f / fmaxf(sqrtf(g_ssq[bh*64 + i]), 1e-12f);
    __syncthreads();
    float rk = 1.f / fmaxf(sqrtf(g_ssk[bh*64 + i]), 1e-12f);
    float rs = rescale[h];
    const float* gp = g_gram + (size_t)bh*4096 + i*64;
    float vals[64];
    float mx = -1e30f;
    #pragma unroll
    for (int j = 0; j < 64; ++j) {
        vals[j] = gp[j] * rk * rq[j] * rs;
        mx = fmaxf(mx, vals[j]);
    }
    float s = 0.f;
    #pragma unroll
    for (int j = 0; j < 64; ++j) { vals[j] = expf(vals[j] - mx); s += vals[j]; }
    float inv = 1.f / s;
    float* ap = g_attn + (size_t)bh*4096 + i*64;
    #pragma unroll
    for (int j = 0; j < 64; ++j) ap[j] = vals[j] * inv;
}

// ------- fold attn into wproj: Wfold[b][h*64+j][o] = sum_i attn[bh,i,j]*wproj[h*64+i][o]
__global__ __launch_bounds__(512) void fold_k(const float* __restrict__ wproj) {
    int b = blockIdx.x >> 9;
    int cj = blockIdx.x & 511;
    int h = cj >> 6, j = cj & 63;
    __shared__ float sa[64];
    int tid = threadIdx.x;
    if (tid < 64) sa[tid] = g_attn[((size_t)(b*8+h)*64 + tid)*64 + j];
    __syncthreads();
    float acc = 0.f;
    #pragma unroll
    for (int i = 0; i < 64; ++i)
        acc = fmaf(sa[i], wproj[(h*64+i)*512 + tid], acc);
    g_wfold[(size_t)b*262144 + cj*512 + tid] = acc;
}

// ---------------- 3x3 depthwise conv, NHWC, SAME zero-pad -------------------
// block: 8x8 spatial tile x 64 channels, smem 10x10x64 with halo.
template<bool DOGELU, bool ADD>
__global__ __launch_bounds__(256) void dwconv_k(const float* __restrict__ in,
                                                const float* __restrict__ wgt,
                                                float* __restrict__ out) {
    __shared__ float tile[100*64];
    int bz = blockIdx.z;
    int b = bz >> 3;
    int c0 = (bz & 7) * 64;
    int y0 = blockIdx.y * 8, x0 = blockIdx.x * 8;
    int tid = threadIdx.x;
    int c = tid & 63;
    int pg = tid >> 6;                   // 0..3
    for (int p = pg; p < 100; p += 4) {
        int gy = y0 - 1 + p/10, gx = x0 - 1 + p%10;
        float v = 0.f;
        if (gy >= 0 && gy < HH && gx >= 0 && gx < WWW)
            v = in[((size_t)(b*HH + gy)*WWW + gx)*CC + c0 + c];
        tile[p*64 + c] = v;
    }
    float w[9];
    #pragma unroll
    for (int t = 0; t < 9; ++t) w[t] = wgt[(c0 + c)*9 + t];
    __syncthreads();
    for (int p = pg; p < 64; p += 4) {
        int oy = p >> 3, ox = p & 7;
        float acc = 0.f;
        #pragma unroll
        for (int dy = 0; dy < 3; ++dy)
            #pragma unroll
            for (int dx = 0; dx < 3; ++dx)
                acc = fmaf(tile[((oy+dy)*10 + ox+dx)*64 + c], w[dy*3+dx], acc);
        if (DOGELU) acc = 0.5f*acc*(1.f + erff(acc*0.70710678118654752f));
        size_t oidx = ((size_t)(b*HH + y0+oy)*WWW + x0+ox)*CC + c0 + c;
        if (ADD) out[oidx] += acc;
        else     out[oidx]  = acc;
    }
}

// ---------------------------------------------------------------------------
extern "C" void kernel_launch(void* const* d_in, const int* in_sizes, int n_in,
                              void* d_out, int out_size) {
    const float* x_in    = (const float*)d_in[0];
    const float* illu    = (const float*)d_in[1];
    const float* prior   = (const float*)d_in[2];
    const float* wq      = (const float*)d_in[3];
    const float* wk      = (const float*)d_in[4];
    const float* wv      = (const float*)d_in[5];
    const float* rescale = (const float*)d_in[6];
    const float* wproj   = (const float*)d_in[7];
    const float* bproj   = (const float*)d_in[8];
    const float* cw1     = (const float*)d_in[9];
    const float* cw2     = (const float*)d_in[10];
    const float* pw1     = (const float*)d_in[11];
    const float* pw2     = (const float*)d_in[12];
    float* out = (float*)d_out;

    float *p_xm, *p_q, *p_k, *p_vi, *p_pe1, *p_tmp, *p_cdp, *p_wfold;
    cudaGetSymbolAddress((void**)&p_xm,    g_xm);
    cudaGetSymbolAddress((void**)&p_q,     g_q);
    cudaGetSymbolAddress((void**)&p_k,     g_k);
    cudaGetSymbolAddress((void**)&p_vi,    g_vi);
    cudaGetSymbolAddress((void**)&p_pe1,   g_pe1);
    cudaGetSymbolAddress((void**)&p_tmp,   g_tmp);
    cudaGetSymbolAddress((void**)&p_cdp,   g_cdp);
    cudaGetSymbolAddress((void**)&p_wfold, g_wfold);

    zero_small_k<<<512, 256>>>();

    // cdp = prior @ cdim_w1 @ cdim_w2
    small_gemm_k<<<(NBATCH*2048 + 255)/256, 256>>>(prior, cw1, p_tmp, 512, 2048);
    small_gemm_k<<<(NBATCH*1024 + 255)/256, 256>>>(p_tmp, cw2, p_cdp, 2048, 1024);

    // xm = x * cdp1 + cdp2
    modulate_k<<<(MTOT*CC/4 + 255)/256, 256>>>(x_in);

    // q, k, v_inp
    dim3 gg(4, 512);
    sgemm_k<false,false><<<gg, 256>>>(p_xm, wq, nullptr, p_q);
    sgemm_k<false,false><<<gg, 256>>>(p_xm, wk, nullptr, p_k);
    sgemm_k<false,false><<<gg, 256>>>(p_xm, wv, nullptr, p_vi);

    // Gram + norms, softmax, fold
    gram_k<<<256, 256>>>();
    softmax_k<<<32, 64>>>(rescale);
    fold_k<<<2048, 512>>>(wproj);

    // v = v_inp * illu (into g_xm), then out_c = v @ Wfold_b + bproj
    vmul_k<<<(MTOT*CC/4 + 255)/256, 256>>>(illu);
    sgemm_k<true,true><<<gg, 256>>>(p_xm, p_wfold, bproj, out);

    // PE branch: out += dwconv(gelu(dwconv(v_inp, pw1)), pw2)
    dim3 cg(WWW/8, HH/8, NBATCH*8);
    dwconv_k<true,false><<<cg, 256>>>(p_vi, pw1, p_pe1);
    dwconv_k<false,true><<<cg, 256>>>(p_pe1, pw2, out);
}

// round 4
// speedup vs baseline: 2.1299x; 2.1299x over previous
#include <cuda_runtime.h>
#include <math.h>
#include <stdint.h>

#define NBATCH 4
#define HH 128
#define WWW 128
#define CC 512
#define NN 16384
#define NHEADS 8
#define DHEAD 64
#define MTOT (NBATCH*NN)

// ---------------- scratch ---------------------------------------------------
__device__ float g_q [MTOT*CC];
__device__ float g_k [MTOT*CC];
__device__ float g_vi[MTOT*CC];
__device__ float g_pe1[MTOT*CC];
__device__ float g_tmp[NBATCH*2048];
__device__ float g_cdp[NBATCH*1024];
__device__ float g_gram[NBATCH*NHEADS*64*64];
__device__ float g_ssq[NBATCH*NHEADS*64];
__device__ float g_ssk[NBATCH*NHEADS*64];
__device__ float g_attn[NBATCH*NHEADS*64*64];
__device__ float g_wt[3*CC*CC];          // transposed wq,wk,wv  [n][k], tf32-rounded
__device__ float g_wfoldt[NBATCH*CC*CC]; // transposed folded proj [b][n][k], tf32-rounded

__device__ __forceinline__ float rna_tf32(float x) {
    uint32_t u;
    asm("cvt.rna.tf32.f32 %0, %1;" : "=r"(u) : "f"(x));
    return __uint_as_float(u);
}

// ---------------- zero accumulators -----------------------------------------
__global__ void zero_small_k() {
    int i = blockIdx.x*blockDim.x + threadIdx.x;
    if (i < NBATCH*NHEADS*64*64) g_gram[i] = 0.f;
    if (i < NBATCH*NHEADS*64) { g_ssq[i] = 0.f; g_ssk[i] = 0.f; }
}

// ---------------- tiny dense (cdp chain) ------------------------------------
__global__ void small_gemm_k(const float* __restrict__ A, const float* __restrict__ Wm,
                             float* __restrict__ out, int K, int Nc) {
    int idx = blockIdx.x*blockDim.x + threadIdx.x;
    if (idx >= NBATCH*Nc) return;
    int b = idx / Nc, j = idx - b*Nc;
    const float* a = A + b*K;
    float acc = 0.f;
    for (int k = 0; k < K; ++k) acc = fmaf(a[k], Wm[k*Nc + j], acc);
    out[idx] = acc;
}

// ---------------- transpose 512x512 with RNA tf32 rounding -------------------
__global__ void transp_k(const float* __restrict__ W, float* __restrict__ Wt) {
    __shared__ float t[32][33];
    int x0 = blockIdx.x*32, y0 = blockIdx.y*32;
    int tx = threadIdx.x, ty = threadIdx.y;
    #pragma unroll
    for (int i = 0; i < 4; ++i)
        t[ty + i*8][tx] = W[(size_t)(y0 + ty + i*8)*512 + x0 + tx];
    __syncthreads();
    #pragma unroll
    for (int i = 0; i < 4; ++i)
        Wt[(size_t)(x0 + ty + i*8)*512 + y0 + tx] = rna_tf32(t[tx][ty + i*8]);
}

// ---------------- mma.sync tf32 GEMM ----------------------------------------
// C[M, n-chunk of 128] = A[M,512] @ Wt^T.  Wt is [n][k] row-major (i.e. B col-major).
// CTA: 256 thr, tile 128(M) x 128(N), K chunks of 32 double-buffered.
// Warps 2(M) x 4(N); warp tile 64x32 via m16n8k8 (4 mtiles x 4 ntiles).
// AMODE: 0 raw, 1 affine (x*cdp1+cdp2), 2 multiply by Aux.
#define KPAD 36
#define ABUF (128*KPAD)               // floats per A stage
#define GEMM_SMEM (4*ABUF*4)          // A0,A1,B0,B1  = 73728 bytes

__device__ __forceinline__ void mma_tf32_16x8x8(
    float& d0, float& d1, float& d2, float& d3,
    float a0, float a1, float a2, float a3, float b0, float b1)
{
    uint32_t const* A = reinterpret_cast<uint32_t const*>(&a0);
    asm volatile(
        "mma.sync.aligned.m16n8k8.row.col.f32.tf32.tf32.f32 "
        "{%0,%1,%2,%3}, {%4,%5,%6,%7}, {%8,%9}, {%0,%1,%2,%3};"
        : "+f"(d0), "+f"(d1), "+f"(d2), "+f"(d3)
        : "r"(__float_as_uint(a0)), "r"(__float_as_uint(a1)),
          "r"(__float_as_uint(a2)), "r"(__float_as_uint(a3)),
          "r"(__float_as_uint(b0)), "r"(__float_as_uint(b1)));
    (void)A;
}

template<int AMODE, int NW, bool PERB, bool BIAS>
__global__ __launch_bounds__(256)
void gemm_mma_k(const float* __restrict__ A, const float* __restrict__ Aux,
                const float* __restrict__ WtB, const float* __restrict__ bias,
                float* __restrict__ C0, float* __restrict__ C1, float* __restrict__ C2)
{
    extern __shared__ __align__(16) float smem[];
    int tid = threadIdx.x;
    int wid = tid >> 5, lane = tid & 31;
    int g = lane >> 2, t = lane & 3;
    int wm = wid & 1, wn = wid >> 1;

    int widx  = blockIdx.x >> 2;          // which weight/output (0..NW-1)
    int ntile = blockIdx.x & 3;           // which 128-wide N chunk
    int n0 = ntile * 128;
    int m0 = blockIdx.y * 128;
    int batch = m0 >> 14;

    const float* Wp = WtB + (size_t)widx*262144 + (PERB ? (size_t)batch*262144 : 0) + (size_t)n0*512;
    float* Cout = (NW == 1) ? C0 : ((widx == 0) ? C0 : (widx == 1) ? C1 : C2);

    float* As[2] = { smem,          smem + ABUF };
    float* Bs[2] = { smem + 2*ABUF, smem + 3*ABUF };

    float acc[4][4][4];
    #pragma unroll
    for (int i = 0; i < 4; ++i)
        #pragma unroll
        for (int j = 0; j < 4; ++j)
            #pragma unroll
            for (int q = 0; q < 4; ++q) acc[i][j][q] = 0.f;

    // ---- A: global->regs (fused elementwise + rna) ----
    float4 areg[4];
    auto ldA = [&](int kt) {
        #pragma unroll
        for (int j = 0; j < 4; ++j) {
            int f = j*256 + tid;
            int row = f >> 3, c4 = f & 7;
            size_t gi = (size_t)(m0 + row)*512 + kt*32 + c4*4;
            float4 v = *(const float4*)(A + gi);
            if (AMODE == 1) {
                int c = kt*32 + c4*4;
                float4 s = *(const float4*)&g_cdp[batch*1024 + c];
                float4 tt = *(const float4*)&g_cdp[batch*1024 + 512 + c];
                v.x = fmaf(v.x, s.x, tt.x); v.y = fmaf(v.y, s.y, tt.y);
                v.z = fmaf(v.z, s.z, tt.z); v.w = fmaf(v.w, s.w, tt.w);
            } else if (AMODE == 2) {
                float4 m = *(const float4*)(Aux + gi);
                v.x *= m.x; v.y *= m.y; v.z *= m.z; v.w *= m.w;
            }
            v.x = rna_tf32(v.x); v.y = rna_tf32(v.y);
            v.z = rna_tf32(v.z); v.w = rna_tf32(v.w);
            areg[j] = v;
        }
    };
    auto stsA = [&](float* dst) {
        #pragma unroll
        for (int j = 0; j < 4; ++j) {
            int f = j*256 + tid;
            int row = f >> 3, c4 = f & 7;
            *(float4*)(dst + row*KPAD + c4*4) = areg[j];
        }
    };
    auto cpB = [&](int kt, float* dst) {
        #pragma unroll
        for (int j = 0; j < 4; ++j) {
            int f = j*256 + tid;
            int n = f >> 3, c4 = f & 7;
            const float* src = Wp + (size_t)n*512 + kt*32 + c4*4;
            float* d = dst + n*KPAD + c4*4;
            asm volatile("cp.async.cg.shared.global [%0], [%1], 16;"
                :: "l"((uint64_t)__cvta_generic_to_shared(d)), "l"(src) : "memory");
        }
        asm volatile("cp.async.commit_group;" ::: "memory");
    };

    // prologue
    ldA(0);
    cpB(0, Bs[0]);

    for (int kt = 0; kt < 16; ++kt) {
        int buf = kt & 1;
        stsA(As[buf]);
        if (kt + 1 < 16) {
            cpB(kt + 1, Bs[buf ^ 1]);
            ldA(kt + 1);
            asm volatile("cp.async.wait_group 1;" ::: "memory");
        } else {
            asm volatile("cp.async.wait_group 0;" ::: "memory");
        }
        __syncthreads();

        const float* Ab = As[buf];
        const float* Bb = Bs[buf];
        #pragma unroll
        for (int kk = 0; kk < 4; ++kk) {
            float af[4][4], bf[4][2];
            #pragma unroll
            for (int mt = 0; mt < 4; ++mt) {
                int base = (wm*64 + mt*16 + g)*KPAD + kk*8 + t;
                af[mt][0] = Ab[base];
                af[mt][1] = Ab[base + 8*KPAD];
                af[mt][2] = Ab[base + 4];
                af[mt][3] = Ab[base + 8*KPAD + 4];
            }
            #pragma unroll
            for (int nt = 0; nt < 4; ++nt) {
                int bbase = (wn*32 + nt*8 + g)*KPAD + kk*8 + t;
                bf[nt][0] = Bb[bbase];
                bf[nt][1] = Bb[bbase + 4];
            }
            #pragma unroll
            for (int mt = 0; mt < 4; ++mt)
                #pragma unroll
                for (int nt = 0; nt < 4; ++nt)
                    mma_tf32_16x8x8(acc[mt][nt][0], acc[mt][nt][1],
                                    acc[mt][nt][2], acc[mt][nt][3],
                                    af[mt][0], af[mt][1], af[mt][2], af[mt][3],
                                    bf[nt][0], bf[nt][1]);
        }
        __syncthreads();
    }

    // ---- epilogue ----
    #pragma unroll
    for (int mt = 0; mt < 4; ++mt) {
        int r0 = m0 + wm*64 + mt*16 + g;
        #pragma unroll
        for (int nt = 0; nt < 4; ++nt) {
            int col = n0 + wn*32 + nt*8 + 2*t;
            float bx = 0.f, by = 0.f;
            if (BIAS) { bx = bias[col]; by = bias[col + 1]; }
            float2 v0 = { acc[mt][nt][0] + bx, acc[mt][nt][1] + by };
            float2 v1 = { acc[mt][nt][2] + bx, acc[mt][nt][3] + by };
            *(float2*)(Cout + (size_t)r0*512 + col)       = v0;
            *(float2*)(Cout + (size_t)(r0 + 8)*512 + col) = v1;
        }
    }
}

// ---------------- Gram + column norms ---------------------------------------
__global__ __launch_bounds__(256) void gram_k() {
    int bh = blockIdx.x >> 3;
    int chunk = blockIdx.x & 7;
    int b = bh >> 3, h = bh & 7;
    int tid = threadIdx.x;
    __shared__ float qs[4][64], ks[4][64];
    float acc[4][4] = {{0.f}};
    float sq = 0.f, sk = 0.f;
    int ti = tid >> 4, tj = tid & 15;
    const float* qbase = g_q + (size_t)b*NN*512 + h*64;
    const float* kbase = g_k + (size_t)b*NN*512 + h*64;
    int n0 = chunk * 2048;
    for (int n = n0; n < n0 + 2048; n += 4) {
        __syncthreads();
        #pragma unroll
        for (int l = tid; l < 512; l += 256) {
            int nn = l >> 7, idx = l & 127;
            if (idx < 64) qs[nn][idx]    = qbase[(size_t)(n+nn)*512 + idx];
            else          ks[nn][idx-64] = kbase[(size_t)(n+nn)*512 + idx - 64];
        }
        __syncthreads();
        #pragma unroll
        for (int nn = 0; nn < 4; ++nn) {
            float kv[4], qv[4];
            #pragma unroll
            for (int ii = 0; ii < 4; ++ii) kv[ii] = ks[nn][ti*4+ii];
            #pragma unroll
            for (int jj = 0; jj < 4; ++jj) qv[jj] = qs[nn][tj*4+jj];
            #pragma unroll
            for (int ii = 0; ii < 4; ++ii)
                #pragma unroll
                for (int jj = 0; jj < 4; ++jj)
                    acc[ii][jj] = fmaf(kv[ii], qv[jj], acc[ii][jj]);
        }
        if (tid < 64) {
            #pragma unroll
            for (int nn = 0; nn < 4; ++nn) sq = fmaf(qs[nn][tid], qs[nn][tid], sq);
        } else if (tid < 128) {
            #pragma unroll
            for (int nn = 0; nn < 4; ++nn) sk = fmaf(ks[nn][tid-64], ks[nn][tid-64], sk);
        }
    }
    float* gp = g_gram + (size_t)bh*4096;
    #pragma unroll
    for (int ii = 0; ii < 4; ++ii)
        #pragma unroll
        for (int jj = 0; jj < 4; ++jj)
            atomicAdd(&gp[(ti*4+ii)*64 + tj*4+jj], acc[ii][jj]);
    if (tid < 64) atomicAdd(&g_ssq[bh*64 + tid], sq);
    else if (tid < 128) atomicAdd(&g_ssk[bh*64 + tid - 64], sk);
}

// ---------------- softmax ----------------------------------------------------
__global__ void softmax_k(const float* __restrict__ rescale) {
    int bh = blockIdx.x;
    int h = bh & 7;
    int i = threadIdx.x;
    __shared__ float rq[64];
    rq[i] = 1.f / fmaxf(sqrtf(g_ssq[bh*64 + i]), 1e-12f);
    __syncthreads();
    float rk = 1.f / fmaxf(sqrtf(g_ssk[bh*64 + i]), 1e-12f);
    float rs = rescale[h];
    const float* gp = g_gram + (size_t)bh*4096 + i*64;
    float vals[64];
    float mx = -1e30f;
    #pragma unroll
    for (int j = 0; j < 64; ++j) {
        vals[j] = gp[j] * rk * rq[j] * rs;
        mx = fmaxf(mx, vals[j]);
    }
    float s = 0.f;
    #pragma unroll
    for (int j = 0; j < 64; ++j) { vals[j] = expf(vals[j] - mx); s += vals[j]; }
    float inv = 1.f / s;
    float* ap = g_attn + (size_t)bh*4096 + i*64;
    #pragma unroll
    for (int j = 0; j < 64; ++j) ap[j] = vals[j] * inv;
}

// ------- fold attn into wproj, TRANSPOSED output (K-major B) -----------------
// Wt_fold[b][o][h*64+j] = sum_i attn[bh,i,j] * wproj[h*64+i][o]
__global__ __launch_bounds__(512) void fold_kT(const float* __restrict__ wproj) {
    int b = blockIdx.x >> 3, h = blockIdx.x & 7;
    int o = threadIdx.x;
    __shared__ float sa[64*64];
    const float* ap = g_attn + (size_t)(b*8 + h)*4096;
    for (int l = o; l < 4096; l += 512) sa[l] = ap[l];
    __syncthreads();
    float wp[64];
    #pragma unroll
    for (int i = 0; i < 64; ++i) wp[i] = wproj[(h*64 + i)*512 + o];
    float* dst = g_wfoldt + (size_t)b*262144 + (size_t)o*512 + h*64;
    #pragma unroll 4
    for (int j = 0; j < 64; ++j) {
        float acc = 0.f;
        #pragma unroll
        for (int i = 0; i < 64; ++i) acc = fmaf(sa[i*64 + j], wp[i], acc);
        dst[j] = rna_tf32(acc);
    }
}

// ---------------- 3x3 depthwise conv, NHWC ----------------------------------
template<bool DOGELU, bool ADD>
__global__ __launch_bounds__(256) void dwconv_k(const float* __restrict__ in,
                                                const float* __restrict__ wgt,
                                                float* __restrict__ out) {
    __shared__ float tile[100*64];
    int bz = blockIdx.z;
    int b = bz >> 3;
    int c0 = (bz & 7) * 64;
    int y0 = blockIdx.y * 8, x0 = blockIdx.x * 8;
    int tid = threadIdx.x;
    int c = tid & 63;
    int pg = tid >> 6;
    for (int p = pg; p < 100; p += 4) {
        int gy = y0 - 1 + p/10, gx = x0 - 1 + p%10;
        float v = 0.f;
        if (gy >= 0 && gy < HH && gx >= 0 && gx < WWW)
            v = in[((size_t)(b*HH + gy)*WWW + gx)*CC + c0 + c];
        tile[p*64 + c] = v;
    }
    float w[9];
    #pragma unroll
    for (int t = 0; t < 9; ++t) w[t] = wgt[(c0 + c)*9 + t];
    __syncthreads();
    for (int p = pg; p < 64; p += 4) {
        int oy = p >> 3, ox = p & 7;
        float acc = 0.f;
        #pragma unroll
        for (int dy = 0; dy < 3; ++dy)
            #pragma unroll
            for (int dx = 0; dx < 3; ++dx)
                acc = fmaf(tile[((oy+dy)*10 + ox+dx)*64 + c], w[dy*3+dx], acc);
        if (DOGELU) acc = 0.5f*acc*(1.f + erff(acc*0.70710678118654752f));
        size_t oidx = ((size_t)(b*HH + y0+oy)*WWW + x0+ox)*CC + c0 + c;
        if (ADD) out[oidx] += acc;
        else     out[oidx]  = acc;
    }
}

// ---------------------------------------------------------------------------
extern "C" void kernel_launch(void* const* d_in, const int* in_sizes, int n_in,
                              void* d_out, int out_size) {
    const float* x_in    = (const float*)d_in[0];
    const float* illu    = (const float*)d_in[1];
    const float* prior   = (const float*)d_in[2];
    const float* wq      = (const float*)d_in[3];
    const float* wk      = (const float*)d_in[4];
    const float* wv      = (const float*)d_in[5];
    const float* rescale = (const float*)d_in[6];
    const float* wproj   = (const float*)d_in[7];
    const float* bproj   = (const float*)d_in[8];
    const float* cw1     = (const float*)d_in[9];
    const float* cw2     = (const float*)d_in[10];
    const float* pw1     = (const float*)d_in[11];
    const float* pw2     = (const float*)d_in[12];
    float* out = (float*)d_out;

    float *p_q, *p_k, *p_vi, *p_pe1, *p_tmp, *p_cdp, *p_wt, *p_wfoldt;
    cudaGetSymbolAddress((void**)&p_q,      g_q);
    cudaGetSymbolAddress((void**)&p_k,      g_k);
    cudaGetSymbolAddress((void**)&p_vi,     g_vi);
    cudaGetSymbolAddress((void**)&p_pe1,    g_pe1);
    cudaGetSymbolAddress((void**)&p_tmp,    g_tmp);
    cudaGetSymbolAddress((void**)&p_cdp,    g_cdp);
    cudaGetSymbolAddress((void**)&p_wt,     g_wt);
    cudaGetSymbolAddress((void**)&p_wfoldt, g_wfoldt);

    cudaFuncSetAttribute(gemm_mma_k<1,3,false,false>,
                         cudaFuncAttributeMaxDynamicSharedMemorySize, GEMM_SMEM);
    cudaFuncSetAttribute(gemm_mma_k<2,1,true,true>,
                         cudaFuncAttributeMaxDynamicSharedMemorySize, GEMM_SMEM);

    zero_small_k<<<512, 256>>>();

    // cdp = prior @ cdim_w1 @ cdim_w2
    small_gemm_k<<<(NBATCH*2048 + 255)/256, 256>>>(prior, cw1, p_tmp, 512, 2048);
    small_gemm_k<<<(NBATCH*1024 + 255)/256, 256>>>(p_tmp, cw2, p_cdp, 2048, 1024);

    // transpose (+tf32 round) weights
    dim3 tb(32, 8), tg(16, 16);
    transp_k<<<tg, tb>>>(wq, p_wt);
    transp_k<<<tg, tb>>>(wk, p_wt + 262144);
    transp_k<<<tg, tb>>>(wv, p_wt + 524288);

    // q,k,v_inp = affine(x) @ W   (mma.sync tf32, fused modulation)
    dim3 gq(12, 512);
    gemm_mma_k<1,3,false,false><<<gq, 256, GEMM_SMEM>>>(
        x_in, nullptr, p_wt, nullptr, p_q, p_k, p_vi);

    // Gram + norms, softmax, fold(+transpose)
    gram_k<<<256, 256>>>();
    softmax_k<<<32, 64>>>(rescale);
    fold_kT<<<32, 512>>>(wproj);

    // out_c = (v_inp*illu) @ Wfold_b + bproj
    dim3 gf(4, 512);
    gemm_mma_k<2,1,true,true><<<gf, 256, GEMM_SMEM>>>(
        p_vi, illu, p_wfoldt, bproj, out, out, out);

    // PE branch: out += dwconv(gelu(dwconv(v_inp, pw1)), pw2)
    dim3 cg(WWW/8, HH/8, NBATCH*8);
    dwconv_k<true,false><<<cg, 256>>>(p_vi, pw1, p_pe1);
    dwconv_k<false,true><<<cg, 256>>>(p_pe1, pw2, out);
}

// round 5
// speedup vs baseline: 2.5942x; 1.2180x over previous
#include <cuda_runtime.h>
#include <cuda_fp16.h>
#include <math.h>
#include <stdint.h>

#define NBATCH 4
#define HH 128
#define WWW 128
#define CC 512
#define NN 16384
#define NHEADS 8
#define DHEAD 64
#define MTOT (NBATCH*NN)

// ---------------- scratch ---------------------------------------------------
__device__ __half g_xh[MTOT*CC];         // modulated x, half
__device__ __half g_vh[MTOT*CC];         // v_inp*illu, half
__device__ __half g_q [MTOT*CC];
__device__ __half g_k [MTOT*CC];
__device__ float  g_vi[MTOT*CC];         // v_inp fp32 (PE branch needs it)
__device__ float  g_pe1[MTOT*CC];
__device__ float  g_tmp[NBATCH*2048];
__device__ float  g_cdp[NBATCH*1024];
__device__ float  g_gram[NBATCH*NHEADS*64*64];
__device__ float  g_ssq[NBATCH*NHEADS*64];
__device__ float  g_ssk[NBATCH*NHEADS*64];
__device__ float  g_attn[NBATCH*NHEADS*64*64];
__device__ __half g_wt[3*CC*CC];         // transposed wq,wk,wv  [n][k]
__device__ __half g_wfoldt[NBATCH*CC*CC];// transposed folded proj [b][n][k]

// ---------------- zero accumulators -----------------------------------------
__global__ void zero_small_k() {
    int i = blockIdx.x*blockDim.x + threadIdx.x;
    if (i < NBATCH*NHEADS*64*64) g_gram[i] = 0.f;
    if (i < NBATCH*NHEADS*64) { g_ssq[i] = 0.f; g_ssk[i] = 0.f; }
}

// ---------------- tiny dense (cdp chain) ------------------------------------
__global__ void small_gemm_k(const float* __restrict__ A, const float* __restrict__ Wm,
                             float* __restrict__ out, int K, int Nc) {
    int idx = blockIdx.x*blockDim.x + threadIdx.x;
    if (idx >= NBATCH*Nc) return;
    int b = idx / Nc, j = idx - b*Nc;
    const float* a = A + b*K;
    float acc = 0.f;
    for (int k = 0; k < K; ++k) acc = fmaf(a[k], Wm[k*Nc + j], acc);
    out[idx] = acc;
}

// ---------------- transpose 512x512 -> half ----------------------------------
__global__ void transp_k(const float* __restrict__ W, __half* __restrict__ Wt) {
    __shared__ float t[32][33];
    int x0 = blockIdx.x*32, y0 = blockIdx.y*32;
    int tx = threadIdx.x, ty = threadIdx.y;
    #pragma unroll
    for (int i = 0; i < 4; ++i)
        t[ty + i*8][tx] = W[(size_t)(y0 + ty + i*8)*512 + x0 + tx];
    __syncthreads();
    #pragma unroll
    for (int i = 0; i < 4; ++i)
        Wt[(size_t)(x0 + ty + i*8)*512 + y0 + tx] = __float2half_rn(t[tx][ty + i*8]);
}

// ---------------- xm = x*cdp1+cdp2 -> half -----------------------------------
__global__ void modulate_k(const float* __restrict__ x) {
    long long i = (long long)blockIdx.x*blockDim.x + threadIdx.x;   // float4 idx
    long long e = i*4;
    int c = (int)(e & (CC-1));
    int b = (int)(e >> 23);
    float4 xv = ((const float4*)x)[i];
    float4 s = *(const float4*)&g_cdp[b*1024 + c];
    float4 t = *(const float4*)&g_cdp[b*1024 + 512 + c];
    __half2 h0 = __floats2half2_rn(fmaf(xv.x, s.x, t.x), fmaf(xv.y, s.y, t.y));
    __half2 h1 = __floats2half2_rn(fmaf(xv.z, s.z, t.z), fmaf(xv.w, s.w, t.w));
    ((__half2*)g_xh)[i*2]   = h0;
    ((__half2*)g_xh)[i*2+1] = h1;
}

// ---------------- vh = v_inp * illu -> half ----------------------------------
__global__ void vmul_k(const float* __restrict__ illu) {
    long long i = (long long)blockIdx.x*blockDim.x + threadIdx.x;
    float4 a = ((const float4*)g_vi)[i];
    float4 m = ((const float4*)illu)[i];
    __half2 h0 = __floats2half2_rn(a.x*m.x, a.y*m.y);
    __half2 h1 = __floats2half2_rn(a.z*m.z, a.w*m.w);
    ((__half2*)g_vh)[i*2]   = h0;
    ((__half2*)g_vh)[i*2+1] = h1;
}

// ---------------- fp16 mma.sync GEMM -----------------------------------------
// C[M, 128-wide n chunk] = A[M,512] @ Wt^T.  A, Wt half; acc fp32.
// CTA 256thr, tile 128x128, K chunks of 32 double buffered via cp.async.
// Warps 2(M)x4(N), warp tile 64x32, m16n8k16.
#define KPADH 40
#define HBUF (128*KPADH)                      // halfs per stage
#define GEMM_SMEM (4*HBUF*2)                  // A0,A1,B0,B1 = 40960 bytes

__device__ __forceinline__ void mma_f16(
    float& d0, float& d1, float& d2, float& d3,
    uint32_t a0, uint32_t a1, uint32_t a2, uint32_t a3, uint32_t b0, uint32_t b1)
{
    asm volatile(
        "mma.sync.aligned.m16n8k16.row.col.f32.f16.f16.f32 "
        "{%0,%1,%2,%3}, {%4,%5,%6,%7}, {%8,%9}, {%0,%1,%2,%3};"
        : "+f"(d0), "+f"(d1), "+f"(d2), "+f"(d3)
        : "r"(a0), "r"(a1), "r"(a2), "r"(a3), "r"(b0), "r"(b1));
}

template<int NW, bool PERB, bool BIAS>
__global__ __launch_bounds__(256)
void gemm_h_k(const __half* __restrict__ A, const __half* __restrict__ WtB,
              const float* __restrict__ bias,
              void* __restrict__ C0, void* __restrict__ C1, void* __restrict__ C2)
{
    extern __shared__ __align__(16) __half smem[];
    int tid = threadIdx.x;
    int wid = tid >> 5, lane = tid & 31;
    int g = lane >> 2, t = lane & 3;
    int wm = wid & 1, wn = wid >> 1;

    int widx  = blockIdx.x >> 2;
    int ntile = blockIdx.x & 3;
    int n0 = ntile * 128;
    int m0 = blockIdx.y * 128;
    int batch = m0 >> 14;

    const __half* Wp = WtB + (size_t)widx*262144 + (PERB ? (size_t)batch*262144 : 0)
                     + (size_t)n0*512;
    bool outhalf = (NW == 3 && widx < 2);
    void* Cout = (NW == 1) ? C0 : ((widx == 0) ? C0 : (widx == 1) ? C1 : C2);

    __half* As[2] = { smem,          smem + HBUF };
    __half* Bs[2] = { smem + 2*HBUF, smem + 3*HBUF };

    float acc[4][4][4];
    #pragma unroll
    for (int i = 0; i < 4; ++i)
        #pragma unroll
        for (int j = 0; j < 4; ++j)
            #pragma unroll
            for (int q = 0; q < 4; ++q) acc[i][j][q] = 0.f;

    auto cpStage = [&](int kt, int buf) {
        // A: 128 rows x 32 half = 512 x 16B;  B same.
        #pragma unroll
        for (int j = 0; j < 2; ++j) {
            int f = j*256 + tid;
            int row = f >> 2, c8 = f & 3;
            const __half* srcA = A + (size_t)(m0 + row)*512 + kt*32 + c8*8;
            __half* dA = As[buf] + row*KPADH + c8*8;
            asm volatile("cp.async.cg.shared.global [%0], [%1], 16;"
                :: "l"((uint64_t)__cvta_generic_to_shared(dA)), "l"(srcA) : "memory");
            const __half* srcB = Wp + (size_t)row*512 + kt*32 + c8*8;
            __half* dB = Bs[buf] + row*KPADH + c8*8;
            asm volatile("cp.async.cg.shared.global [%0], [%1], 16;"
                :: "l"((uint64_t)__cvta_generic_to_shared(dB)), "l"(srcB) : "memory");
        }
        asm volatile("cp.async.commit_group;" ::: "memory");
    };

    cpStage(0, 0);

    for (int kt = 0; kt < 16; ++kt) {
        int buf = kt & 1;
        if (kt + 1 < 16) {
            cpStage(kt + 1, buf ^ 1);
            asm volatile("cp.async.wait_group 1;" ::: "memory");
        } else {
            asm volatile("cp.async.wait_group 0;" ::: "memory");
        }
        __syncthreads();

        const __half* Ab = As[buf];
        const __half* Bb = Bs[buf];
        #pragma unroll
        for (int kk = 0; kk < 2; ++kk) {
            uint32_t af[4][4], bf[4][2];
            #pragma unroll
            for (int mt = 0; mt < 4; ++mt) {
                int r = wm*64 + mt*16 + g;
                const __half* p = Ab + r*KPADH + kk*16 + 2*t;
                af[mt][0] = *(const uint32_t*)(p);
                af[mt][1] = *(const uint32_t*)(p + 8*KPADH);
                af[mt][2] = *(const uint32_t*)(p + 8);
                af[mt][3] = *(const uint32_t*)(p + 8*KPADH + 8);
            }
            #pragma unroll
            for (int nt = 0; nt < 4; ++nt) {
                int r = wn*32 + nt*8 + g;
                const __half* p = Bb + r*KPADH + kk*16 + 2*t;
                bf[nt][0] = *(const uint32_t*)(p);
                bf[nt][1] = *(const uint32_t*)(p + 8);
            }
            #pragma unroll
            for (int mt = 0; mt < 4; ++mt)
                #pragma unroll
                for (int nt = 0; nt < 4; ++nt)
                    mma_f16(acc[mt][nt][0], acc[mt][nt][1],
                            acc[mt][nt][2], acc[mt][nt][3],
                            af[mt][0], af[mt][1], af[mt][2], af[mt][3],
                            bf[nt][0], bf[nt][1]);
        }
        __syncthreads();
    }

    // ---- epilogue ----
    #pragma unroll
    for (int mt = 0; mt < 4; ++mt) {
        int r0 = m0 + wm*64 + mt*16 + g;
        #pragma unroll
        for (int nt = 0; nt < 4; ++nt) {
            int col = n0 + wn*32 + nt*8 + 2*t;
            if (outhalf) {
                __half2 h0 = __floats2half2_rn(acc[mt][nt][0], acc[mt][nt][1]);
                __half2 h1 = __floats2half2_rn(acc[mt][nt][2], acc[mt][nt][3]);
                *(__half2*)((__half*)Cout + (size_t)r0*512 + col)       = h0;
                *(__half2*)((__half*)Cout + (size_t)(r0+8)*512 + col)   = h1;
            } else {
                float bx = 0.f, by = 0.f;
                if (BIAS) { bx = bias[col]; by = bias[col + 1]; }
                float2 v0 = { acc[mt][nt][0] + bx, acc[mt][nt][1] + by };
                float2 v1 = { acc[mt][nt][2] + bx, acc[mt][nt][3] + by };
                *(float2*)((float*)Cout + (size_t)r0*512 + col)     = v0;
                *(float2*)((float*)Cout + (size_t)(r0+8)*512 + col) = v1;
            }
        }
    }
}

// ---------------- Gram + column norms (half inputs) --------------------------
__global__ __launch_bounds__(256) void gram_k() {
    int bh = blockIdx.x >> 3;
    int chunk = blockIdx.x & 7;
    int b = bh >> 3, h = bh & 7;
    int tid = threadIdx.x;
    __shared__ float qs[4][64], ks[4][64];
    float acc[4][4] = {{0.f}};
    float sq = 0.f, sk = 0.f;
    int ti = tid >> 4, tj = tid & 15;
    const __half* qbase = g_q + (size_t)b*NN*512 + h*64;
    const __half* kbase = g_k + (size_t)b*NN*512 + h*64;
    int n0 = chunk * 2048;
    int lnn = tid >> 5 & 3, lj = (tid & 31) * 2;
    bool isq = tid < 128;
    for (int n = n0; n < n0 + 2048; n += 4) {
        __syncthreads();
        {
            const __half* src = isq ? qbase : kbase;
            __half2 hv = *(const __half2*)(src + (size_t)(n + lnn)*512 + lj);
            float2 fv = __half22float2(hv);
            float* dst = isq ? &qs[lnn][lj] : &ks[lnn][lj];
            dst[0] = fv.x; dst[1] = fv.y;
        }
        __syncthreads();
        #pragma unroll
        for (int nn = 0; nn < 4; ++nn) {
            float kv[4], qv[4];
            #pragma unroll
            for (int ii = 0; ii < 4; ++ii) kv[ii] = ks[nn][ti*4+ii];
            #pragma unroll
            for (int jj = 0; jj < 4; ++jj) qv[jj] = qs[nn][tj*4+jj];
            #pragma unroll
            for (int ii = 0; ii < 4; ++ii)
                #pragma unroll
                for (int jj = 0; jj < 4; ++jj)
                    acc[ii][jj] = fmaf(kv[ii], qv[jj], acc[ii][jj]);
        }
        if (tid < 64) {
            #pragma unroll
            for (int nn = 0; nn < 4; ++nn) sq = fmaf(qs[nn][tid], qs[nn][tid], sq);
        } else if (tid < 128) {
            #pragma unroll
            for (int nn = 0; nn < 4; ++nn) sk = fmaf(ks[nn][tid-64], ks[nn][tid-64], sk);
        }
    }
    float* gp = g_gram + (size_t)bh*4096;
    #pragma unroll
    for (int ii = 0; ii < 4; ++ii)
        #pragma unroll
        for (int jj = 0; jj < 4; ++jj)
            atomicAdd(&gp[(ti*4+ii)*64 + tj*4+jj], acc[ii][jj]);
    if (tid < 64) atomicAdd(&g_ssq[bh*64 + tid], sq);
    else if (tid < 128) atomicAdd(&g_ssk[bh*64 + tid - 64], sk);
}

// ---------------- softmax ----------------------------------------------------
__global__ void softmax_k(const float* __restrict__ rescale) {
    int bh = blockIdx.x;
    int h = bh & 7;
    int i = threadIdx.x;
    __shared__ float rq[64];
    rq[i] = 1.f / fmaxf(sqrtf(g_ssq[bh*64 + i]), 1e-12f);
    __syncthreads();
    float rk = 1.f / fmaxf(sqrtf(g_ssk[bh*64 + i]), 1e-12f);
    float rs = rescale[h];
    const float* gp = g_gram + (size_t)bh*4096 + i*64;
    float vals[64];
    float mx = -1e30f;
    #pragma unroll
    for (int j = 0; j < 64; ++j) {
        vals[j] = gp[j] * rk * rq[j] * rs;
        mx = fmaxf(mx, vals[j]);
    }
    float s = 0.f;
    #pragma unroll
    for (int j = 0; j < 64; ++j) { vals[j] = expf(vals[j] - mx); s += vals[j]; }
    float inv = 1.f / s;
    float* ap = g_attn + (size_t)bh*4096 + i*64;
    #pragma unroll
    for (int j = 0; j < 64; ++j) ap[j] = vals[j] * inv;
}

// ------- fold attn into wproj, TRANSPOSED half output ------------------------
__global__ __launch_bounds__(512) void fold_kT(const float* __restrict__ wproj) {
    int b = blockIdx.x >> 3, h = blockIdx.x & 7;
    int o = threadIdx.x;
    __shared__ float sa[64*64];
    const float* ap = g_attn + (size_t)(b*8 + h)*4096;
    for (int l = o; l < 4096; l += 512) sa[l] = ap[l];
    __syncthreads();
    float wp[64];
    #pragma unroll
    for (int i = 0; i < 64; ++i) wp[i] = wproj[(h*64 + i)*512 + o];
    __half* dst = g_wfoldt + (size_t)b*262144 + (size_t)o*512 + h*64;
    #pragma unroll 4
    for (int j = 0; j < 64; ++j) {
        float acc = 0.f;
        #pragma unroll
        for (int i = 0; i < 64; ++i) acc = fmaf(sa[i*64 + j], wp[i], acc);
        dst[j] = __float2half_rn(acc);
    }
}

// ---------------- 3x3 depthwise conv, NHWC ----------------------------------
template<bool DOGELU, bool ADD>
__global__ __launch_bounds__(256) void dwconv_k(const float* __restrict__ in,
                                                const float* __restrict__ wgt,
                                                float* __restrict__ out) {
    __shared__ float tile[100*64];
    int bz = blockIdx.z;
    int b = bz >> 3;
    int c0 = (bz & 7) * 64;
    int y0 = blockIdx.y * 8, x0 = blockIdx.x * 8;
    int tid = threadIdx.x;
    int c = tid & 63;
    int pg = tid >> 6;
    for (int p = pg; p < 100; p += 4) {
        int gy = y0 - 1 + p/10, gx = x0 - 1 + p%10;
        float v = 0.f;
        if (gy >= 0 && gy < HH && gx >= 0 && gx < WWW)
            v = in[((size_t)(b*HH + gy)*WWW + gx)*CC + c0 + c];
        tile[p*64 + c] = v;
    }
    float w[9];
    #pragma unroll
    for (int t = 0; t < 9; ++t) w[t] = wgt[(c0 + c)*9 + t];
    __syncthreads();
    for (int p = pg; p < 64; p += 4) {
        int oy = p >> 3, ox = p & 7;
        float acc = 0.f;
        #pragma unroll
        for (int dy = 0; dy < 3; ++dy)
            #pragma unroll
            for (int dx = 0; dx < 3; ++dx)
                acc = fmaf(tile[((oy+dy)*10 + ox+dx)*64 + c], w[dy*3+dx], acc);
        if (DOGELU) acc = 0.5f*acc*(1.f + erff(acc*0.70710678118654752f));
        size_t oidx = ((size_t)(b*HH + y0+oy)*WWW + x0+ox)*CC + c0 + c;
        if (ADD) out[oidx] += acc;
        else     out[oidx]  = acc;
    }
}

// ---------------------------------------------------------------------------
extern "C" void kernel_launch(void* const* d_in, const int* in_sizes, int n_in,
                              void* d_out, int out_size) {
    const float* x_in    = (const float*)d_in[0];
    const float* illu    = (const float*)d_in[1];
    const float* prior   = (const float*)d_in[2];
    const float* wq      = (const float*)d_in[3];
    const float* wk      = (const float*)d_in[4];
    const float* wv      = (const float*)d_in[5];
    const float* rescale = (const float*)d_in[6];
    const float* wproj   = (const float*)d_in[7];
    const float* bproj   = (const float*)d_in[8];
    const float* cw1     = (const float*)d_in[9];
    const float* cw2     = (const float*)d_in[10];
    const float* pw1     = (const float*)d_in[11];
    const float* pw2     = (const float*)d_in[12];
    float* out = (float*)d_out;

    float *p_vi, *p_pe1, *p_tmp, *p_cdp;
    __half *p_xh, *p_vh, *p_q, *p_k, *p_wt, *p_wfoldt;
    cudaGetSymbolAddress((void**)&p_xh,     g_xh);
    cudaGetSymbolAddress((void**)&p_vh,     g_vh);
    cudaGetSymbolAddress((void**)&p_q,      g_q);
    cudaGetSymbolAddress((void**)&p_k,      g_k);
    cudaGetSymbolAddress((void**)&p_vi,     g_vi);
    cudaGetSymbolAddress((void**)&p_pe1,    g_pe1);
    cudaGetSymbolAddress((void**)&p_tmp,    g_tmp);
    cudaGetSymbolAddress((void**)&p_cdp,    g_cdp);
    cudaGetSymbolAddress((void**)&p_wt,     g_wt);
    cudaGetSymbolAddress((void**)&p_wfoldt, g_wfoldt);

    cudaFuncSetAttribute(gemm_h_k<3,false,false>,
                         cudaFuncAttributeMaxDynamicSharedMemorySize, GEMM_SMEM);
    cudaFuncSetAttribute(gemm_h_k<1,true,true>,
                         cudaFuncAttributeMaxDynamicSharedMemorySize, GEMM_SMEM);

    zero_small_k<<<512, 256>>>();

    // cdp = prior @ cdim_w1 @ cdim_w2
    small_gemm_k<<<(NBATCH*2048 + 255)/256, 256>>>(prior, cw1, p_tmp, 512, 2048);
    small_gemm_k<<<(NBATCH*1024 + 255)/256, 256>>>(p_tmp, cw2, p_cdp, 2048, 1024);

    // weights -> transposed half
    dim3 tb(32, 8), tg(16, 16);
    transp_k<<<tg, tb>>>(wq, p_wt);
    transp_k<<<tg, tb>>>(wk, p_wt + 262144);
    transp_k<<<tg, tb>>>(wv, p_wt + 524288);

    // xm (half) = x*cdp1 + cdp2
    modulate_k<<<(MTOT*CC/4 + 255)/256, 256>>>(x_in);

    // q,k (half), v_inp (fp32) = xm @ W
    dim3 gq(12, 512);
    gemm_h_k<3,false,false><<<gq, 256, GEMM_SMEM>>>(
        p_xh, p_wt, nullptr, p_q, p_k, p_vi);

    // Gram + norms, softmax, fold(+transpose, half)
    gram_k<<<256, 256>>>();
    softmax_k<<<32, 64>>>(rescale);
    fold_kT<<<32, 512>>>(wproj);

    // vh = v_inp * illu (half)
    vmul_k<<<(MTOT*CC/4 + 255)/256, 256>>>(illu);

    // out_c = vh @ Wfold_b + bproj
    dim3 gf(4, 512);
    gemm_h_k<1,true,true><<<gf, 256, GEMM_SMEM>>>(
        p_vh, p_wfoldt, bproj, out, out, out);

    // PE branch: out += dwconv(gelu(dwconv(v_inp, pw1)), pw2)
    dim3 cg(WWW/8, HH/8, NBATCH*8);
    dwconv_k<true,false><<<cg, 256>>>(p_vi, pw1, p_pe1);
    dwconv_k<false,true><<<cg, 256>>>(p_pe1, pw2, out);
}